// round 3
// baseline (speedup 1.0000x reference)
#include <cuda_runtime.h>

// Global scratch: 5x5 confusion matrix as unsigned counts.
__device__ unsigned int g_conf[25];

__global__ void zero_conf_kernel() {
    if (threadIdx.x < 25) g_conf[threadIdx.x] = 0u;
}

__device__ __forceinline__ int soft_pred(float x0, float x1, float x2, float x3, float x4) {
    float m = fmaxf(fmaxf(fmaxf(x0, x1), fmaxf(x2, x3)), x4);
    float e0 = __expf(x0 - m);
    float e1 = __expf(x1 - m);
    float e2 = __expf(x2 - m);
    float e3 = __expf(x3 - m);
    float e4 = __expf(x4 - m);
    float s  = e0 + e1 + e2 + e3 + e4;
    float sa = (e1 + 2.0f * e2 + 3.0f * e3 + 4.0f * e4) / s;
    int p = __float2int_rn(sa);      // round half-to-even, matches jnp.round
    p = max(0, min(4, p));
    return p;
}

__global__ void kappa_main_kernel(const float* __restrict__ preds,
                                  const int* __restrict__ labels,
                                  int n) {
    __shared__ unsigned int sconf[25];
    if (threadIdx.x < 25) sconf[threadIdx.x] = 0u;
    __syncthreads();

    const int groups = n >> 2;                 // 4 rows per group (20 floats = 5 float4)
    const int stride = gridDim.x * blockDim.x;
    const float4* __restrict__ p4base = reinterpret_cast<const float4*>(preds);
    const int4*   __restrict__ t4base = reinterpret_cast<const int4*>(labels);

    for (int g = blockIdx.x * blockDim.x + threadIdx.x; g < groups; g += stride) {
        const float4* p4 = p4base + (size_t)g * 5;
        float4 a = p4[0];
        float4 b = p4[1];
        float4 c = p4[2];
        float4 d = p4[3];
        float4 e = p4[4];
        int4 t = t4base[g];

        int p0 = soft_pred(a.x, a.y, a.z, a.w, b.x);
        int p1 = soft_pred(b.y, b.z, b.w, c.x, c.y);
        int p2 = soft_pred(c.z, c.w, d.x, d.y, d.z);
        int p3 = soft_pred(d.w, e.x, e.y, e.z, e.w);

        atomicAdd(&sconf[t.x * 5 + p0], 1u);
        atomicAdd(&sconf[t.y * 5 + p1], 1u);
        atomicAdd(&sconf[t.z * 5 + p2], 1u);
        atomicAdd(&sconf[t.w * 5 + p3], 1u);
    }

    // Tail rows (n not a multiple of 4) — handled by one thread.
    if (blockIdx.x == 0 && threadIdx.x == 0) {
        for (int i = (groups << 2); i < n; ++i) {
            const float* r = preds + (size_t)i * 5;
            int p = soft_pred(r[0], r[1], r[2], r[3], r[4]);
            atomicAdd(&sconf[labels[i] * 5 + p], 1u);
        }
    }

    __syncthreads();
    if (threadIdx.x < 25) {
        unsigned int v = sconf[threadIdx.x];
        if (v) atomicAdd(&g_conf[threadIdx.x], v);
    }
}

__global__ void kappa_finalize_kernel(float* __restrict__ out, int n) {
    if (threadIdx.x == 0 && blockIdx.x == 0) {
        double cf[25];
        double th[5] = {0, 0, 0, 0, 0};
        double ph[5] = {0, 0, 0, 0, 0};
        #pragma unroll
        for (int i = 0; i < 25; ++i) cf[i] = (double)g_conf[i];
        #pragma unroll
        for (int i = 0; i < 5; ++i)
            #pragma unroll
            for (int j = 0; j < 5; ++j) {
                th[i] += cf[i * 5 + j];
                ph[j] += cf[i * 5 + j];
            }
        double num = 0.0, den = 0.0;
        #pragma unroll
        for (int i = 0; i < 5; ++i)
            #pragma unroll
            for (int j = 0; j < 5; ++j) {
                double w = (double)((i - j) * (i - j)) / 16.0;
                num += cf[i * 5 + j] * w;
                den += th[i] * ph[j] * w;
            }
        // result = (num/N) / (den/N^2) = num * N / den
        out[0] = (float)(num * (double)n / den);
    }
}

extern "C" void kernel_launch(void* const* d_in, const int* in_sizes, int n_in,
                              void* d_out, int out_size) {
    const float* preds  = (const float*)d_in[0];
    const int*   labels = (const int*)d_in[1];
    const int n = in_sizes[1];                  // number of samples

    zero_conf_kernel<<<1, 32>>>();

    const int threads = 256;
    int groups = n >> 2;
    int blocks = (groups + threads - 1) / threads;
    const int max_blocks = 148 * 16;            // ~3.3 groups/thread at N=8M
    if (blocks > max_blocks) blocks = max_blocks;
    if (blocks < 1) blocks = 1;
    kappa_main_kernel<<<blocks, threads>>>(preds, labels, n);

    kappa_finalize_kernel<<<1, 32>>>((float*)d_out, n);
}